// round 7
// baseline (speedup 1.0000x reference)
#include <cuda_runtime.h>
#include <cuda_bf16.h>

#define L 2048
#define LMASK 2047
#define LSHIFT 11
#define PAIRMASK 0x5A48u
#define CAP 192            // finish smem-cache capacity

// ---------------- device scratch ----------------
__device__ float d_C[(size_t)L * L];          // compacted active x active matrix
__device__ unsigned long long d_best[L];      // per-vertex / per-local-row best priority
__device__ int d_cls[L];
__device__ int d_act[L];                      // global ids of round-1 survivors (ascending)
__device__ int d_nAct;
__device__ int d_lact[2][L];                  // ping-pong local-id lists
__device__ int d_nL[2];

__device__ __forceinline__ unsigned long long pack_g(float s, int a, int b) {
    unsigned k = (unsigned)(a * L + b);
    return ((unsigned long long)__float_as_uint(s) << 32) | (unsigned long long)(~k);
}
__device__ __forceinline__ unsigned long long pack_l(float s, int lo, int hi) {
    unsigned k = ((unsigned)lo << LSHIFT) | (unsigned)hi;
    return ((unsigned long long)__float_as_uint(s) << 32) | (unsigned long long)(~k);
}
__device__ __forceinline__ unsigned long long warp_max(unsigned long long m) {
    #pragma unroll
    for (int o = 16; o; o >>= 1) {
        unsigned long long q = __shfl_xor_sync(0xFFFFFFFFu, m, o);
        if (q > m) m = q;
    }
    return m;
}
// triangular block map: k -> (bi, bj) with bi <= bj
__device__ __forceinline__ void tri_map(int k, int& bi, int& bj) {
    int b = (int)((__fsqrt_rn(8.0f * (float)k + 1.0f) - 1.0f) * 0.5f);
    while (b * (b + 1) / 2 > k) b--;
    while ((b + 1) * (b + 2) / 2 <= k) b++;
    bj = b;
    bi = k - b * (b + 1) / 2;
}

// ---------------- K1: classes + clear best ----------------
__global__ void kern_cls(const float* __restrict__ feat) {
    int i = blockIdx.x * blockDim.x + threadIdx.x;
    if (i >= L) return;
    float f0 = feat[(size_t)i * L];
    float f1 = feat[(size_t)L * L + (size_t)i * L];
    float f2 = feat[2 * (size_t)L * L + (size_t)i * L];
    float f3 = feat[3 * (size_t)L * L + (size_t)i * L];
    int c = 0; float m = f0;
    if (f1 > m) { m = f1; c = 1; }
    if (f2 > m) { m = f2; c = 2; }
    if (f3 > m) { m = f3; c = 3; }
    d_cls[i] = c;
    d_best[i] = 0ULL;
}

// ---------------- K2: round-1 best + zero output (triangular grid, 32x32 tiles) ----------------
__global__ void kern_build(const float* __restrict__ con, float* __restrict__ out) {
    int bi, bj; tri_map(blockIdx.x, bi, bj);      // bi <= bj

    __shared__ float sB[32][33];
    __shared__ int clsR[32], clsC[32];

    int tx = threadIdx.x, ty = threadIdx.y;
    int i = bi * 32 + ty;
    int j = bj * 32 + tx;

    if (ty == 0) { clsR[tx] = d_cls[bi * 32 + tx]; clsC[tx] = d_cls[bj * 32 + tx]; }

    float a = con[(size_t)i * L + j];
    sB[ty][tx] = con[(size_t)(bj * 32 + ty) * L + (bi * 32 + tx)];
    __syncthreads();

    float b = sB[tx][ty];          // con[j][i]
    float v = 0.5f * (a + b);
    int d = j - i;
    bool band = (d >= 4) || (d <= -4);
    bool pm = (PAIRMASK >> ((clsR[ty] << 2) | clsC[tx])) & 1u;
    float s = (band && pm) ? v : 0.0f;

    out[(size_t)i * L + j] = 0.0f;
    out[(size_t)(bj * 32 + ty) * L + (bi * 32 + tx)] = 0.0f;

    // row max (vertex i): pairs (i, j) with j > i
    unsigned long long p = (s > 0.0f && j > i) ? pack_g(s, i, j) : 0ULL;
    unsigned long long m = warp_max(p);
    if (tx == 0 && m) atomicMax(&d_best[i], m);

    // transpose s via sB reuse; recompute priority for column reduction
    __syncthreads();
    sB[ty][tx] = s;
    __syncthreads();
    float s2 = sB[tx][ty];                 // pair (i2 = bi*32+tx, j2 = bj*32+ty)
    int i2 = bi * 32 + tx, j2 = bj * 32 + ty;
    unsigned long long p2 = (s2 > 0.0f && j2 > i2) ? pack_g(s2, i2, j2) : 0ULL;
    unsigned long long cm = warp_max(p2);
    if (tx == 0 && cm) atomicMax(&d_best[j2], cm);
}

// ---------------- K3: round-1 take, build d_act, clear best ----------------
__global__ void kern_take1(float* __restrict__ out) {
    __shared__ int wsum[32];
    __shared__ int sTotal;
    int t = threadIdx.x;
    int lane = t & 31, wid = t >> 5;

    int f[2]; int vv[2];
    #pragma unroll
    for (int r = 0; r < 2; r++) {
        int v = 2 * t + r;
        int fl = 0;
        unsigned long long b = d_best[v];
        if (b) {
            unsigned k = ~((unsigned)b);
            int i = (int)(k >> LSHIFT), j = (int)(k & LMASK);
            int u = (v == i) ? j : i;
            if (d_best[u] == b) {
                if (v == i) {
                    float val = __uint_as_float((unsigned)(b >> 32));
                    out[i * L + j] = val;
                    out[j * L + i] = val;
                }
            } else fl = 1;
        }
        f[r] = fl; vv[r] = v;
    }

    int sum = f[0] + f[1];
    int x = sum;
    #pragma unroll
    for (int o = 1; o < 32; o <<= 1) { int y = __shfl_up_sync(0xFFFFFFFFu, x, o); if (lane >= o) x += y; }
    if (lane == 31) wsum[wid] = x;
    __syncthreads();
    if (wid == 0) {
        int z = wsum[lane];
        #pragma unroll
        for (int o = 1; o < 32; o <<= 1) { int y = __shfl_up_sync(0xFFFFFFFFu, z, o); if (lane >= o) z += y; }
        wsum[lane] = z;
        if (lane == 31) sTotal = z;
    }
    __syncthreads();
    int ex = (wid ? wsum[wid - 1] : 0) + x - sum;
    if (f[0]) d_act[ex] = vv[0];
    if (f[1]) d_act[ex + f[0]] = vv[1];
    if (t == 0) d_nAct = sTotal;

    // clear for compact's local atomicMax (all d_best reads are above)
    d_best[2 * t] = 0ULL;
    d_best[2 * t + 1] = 0ULL;
}

// ---------------- K4: 64x64-tile gather of C + fused round-2 best (triangular grid) ----------------
// 2x2 elements per thread: 8 independent gathered loads -> high MLP.
__global__ void kern_compact(const float* __restrict__ con) {
    int n = d_nAct;
    int bi, bj; tri_map(blockIdx.x, bi, bj);      // 64-tiles, bi <= bj
    if (bi * 64 >= n || bj * 64 >= n) return;
    int ns = (n + 31) & ~31;

    __shared__ float sT[64][65];
    __shared__ int gA[64], gB[64], cA[64], cB[64];

    int tx = threadIdx.x, ty = threadIdx.y;
    int t = ty * 32 + tx;
    if (t < 64) {
        int a = bi * 64 + t;
        int va = (a < n) ? d_act[a] : -1;
        gA[t] = va; cA[t] = (va >= 0) ? d_cls[va] : 0;
    } else if (t < 128) {
        int q = t - 64, b = bj * 64 + q;
        int vb = (b < n) ? d_act[b] : -1;
        gB[q] = vb; cB[q] = (vb >= 0) ? d_cls[vb] : 0;
    }
    __syncthreads();

    int vaR[2] = { gA[ty], gA[ty + 32] };
    int vbR[2] = { gB[tx], gB[tx + 32] };
    int caR[2] = { cA[ty], cA[ty + 32] };
    int cbR[2] = { cB[tx], cB[tx + 32] };

    // direct tile: x[ry][rx] = con[va][vb]  (row-local gathers)
    float x[2][2];
    #pragma unroll
    for (int ry = 0; ry < 2; ry++)
        #pragma unroll
        for (int rx = 0; rx < 2; rx++)
            x[ry][rx] = (vaR[ry] >= 0 && vbR[rx] >= 0)
                      ? con[(size_t)vaR[ry] * L + vbR[rx]] : 0.0f;

    // transposed source tile into smem: sT[q][p] = con[gB[q]][gA[p]]  (row-local gathers)
    {
        int wy[2] = { gB[ty], gB[ty + 32] };
        int ua[2] = { gA[tx], gA[tx + 32] };
        #pragma unroll
        for (int ry = 0; ry < 2; ry++)
            #pragma unroll
            for (int rx = 0; rx < 2; rx++)
                sT[ty + 32 * ry][tx + 32 * rx] =
                    (wy[ry] >= 0 && ua[rx] >= 0)
                  ? con[(size_t)wy[ry] * L + ua[rx]] : 0.0f;
    }
    __syncthreads();

    // masked symmetric value, direct C write, row max
    float s[2][2];
    #pragma unroll
    for (int ry = 0; ry < 2; ry++) {
        int a = bi * 64 + ty + 32 * ry;
        unsigned long long m = 0ULL;
        #pragma unroll
        for (int rx = 0; rx < 2; rx++) {
            int b = bj * 64 + tx + 32 * rx;
            float v = 0.5f * (x[ry][rx] + sT[tx + 32 * rx][ty + 32 * ry]);
            float sv = 0.0f;
            if (vaR[ry] >= 0 && vbR[rx] >= 0) {
                int d = vaR[ry] - vbR[rx];
                bool band = (d >= 4) || (d <= -4);
                bool pm = (PAIRMASK >> ((caR[ry] << 2) | cbR[rx])) & 1u;
                sv = (band && pm) ? v : 0.0f;
            }
            s[ry][rx] = sv;
            if (a < n && b < n) d_C[(size_t)a * ns + b] = sv;   // coalesced over tx
            if (sv > 0.0f && b > a) {
                unsigned long long p = pack_l(sv, a, b);
                if (p > m) m = p;
            }
        }
        m = warp_max(m);
        if (tx == 0 && m) atomicMax(&d_best[a], m);
    }

    // transpose s via smem: mirrored C write + column reduction
    __syncthreads();
    #pragma unroll
    for (int ry = 0; ry < 2; ry++)
        #pragma unroll
        for (int rx = 0; rx < 2; rx++)
            sT[ty + 32 * ry][tx + 32 * rx] = s[ry][rx];
    __syncthreads();

    #pragma unroll
    for (int ry = 0; ry < 2; ry++) {
        int b2 = bj * 64 + ty + 32 * ry;
        unsigned long long m = 0ULL;
        #pragma unroll
        for (int rx = 0; rx < 2; rx++) {
            int a2 = bi * 64 + tx + 32 * rx;
            float s2 = sT[tx + 32 * rx][ty + 32 * ry];
            if (b2 < n && a2 < n) d_C[(size_t)b2 * ns + a2] = s2;   // coalesced over tx
            if (s2 > 0.0f && b2 > a2) {
                unsigned long long p = pack_l(s2, a2, b2);
                if (p > m) m = p;
            }
        }
        m = warp_max(m);
        if (tx == 0 && m) atomicMax(&d_best[b2], m);
    }
}

// ---------------- K5: local-space take (1 block) ----------------
// srcSel < 0: identity list 0..d_nAct
__global__ void kern_takeL(int srcSel, int dstSel, float* __restrict__ out) {
    __shared__ int wsum[32];
    __shared__ int sTotal;
    int t = threadIdx.x;
    int lane = t & 31, wid = t >> 5;
    int n = (srcSel < 0) ? d_nAct : d_nL[srcSel];
    const int* lst = (srcSel < 0) ? 0 : d_lact[srcSel];

    int f[2]; int vv[2];
    #pragma unroll
    for (int r = 0; r < 2; r++) {
        int idx = 2 * t + r;
        int fl = 0, la = -1;
        if (idx < n) {
            la = lst ? lst[idx] : idx;
            unsigned long long b = d_best[la];
            if (b) {
                unsigned k = ~((unsigned)b);
                int lo = (int)(k >> LSHIFT), hi = (int)(k & LMASK);
                int lu = (la == lo) ? hi : lo;
                if (d_best[lu] == b) {
                    if (la == lo) {
                        float val = __uint_as_float((unsigned)(b >> 32));
                        int gi = d_act[lo], gj = d_act[hi];
                        out[gi * L + gj] = val;
                        out[gj * L + gi] = val;
                    }
                } else fl = 1;
            }
        }
        f[r] = fl; vv[r] = la;
    }

    int sum = f[0] + f[1];
    int x = sum;
    #pragma unroll
    for (int o = 1; o < 32; o <<= 1) { int y = __shfl_up_sync(0xFFFFFFFFu, x, o); if (lane >= o) x += y; }
    if (lane == 31) wsum[wid] = x;
    __syncthreads();
    if (wid == 0) {
        int z = wsum[lane];
        #pragma unroll
        for (int o = 1; o < 32; o <<= 1) { int y = __shfl_up_sync(0xFFFFFFFFu, z, o); if (lane >= o) z += y; }
        wsum[lane] = z;
        if (lane == 31) sTotal = z;
    }
    __syncthreads();
    int ex = (wid ? wsum[wid - 1] : 0) + x - sum;
    if (f[0]) d_lact[dstSel][ex] = vv[0];
    if (f[1]) d_lact[dstSel][ex + f[0]] = vv[1];
    if (t == 0) d_nL[dstSel] = sTotal;
}

// ---------------- K6: local-space best over C (multi-CTA, warp per row) ----------------
__global__ void kern_bestL(int sel) {
    __shared__ int sAct[L];
    int n = d_nL[sel];
    if (n == 0) return;
    int ns = (d_nAct + 31) & ~31;
    const int* lst = d_lact[sel];
    for (int t = threadIdx.x; t < n; t += blockDim.x) sAct[t] = lst[t];
    __syncthreads();

    int lane = threadIdx.x & 31;
    int gw = (blockIdx.x * blockDim.x + threadIdx.x) >> 5;
    int tw = (gridDim.x * blockDim.x) >> 5;

    for (int a = gw; a < n; a += tw) {
        int la = sAct[a];
        const float* __restrict__ row = d_C + (size_t)la * ns;
        unsigned long long m = 0ULL;
        for (int l = lane; l < n; l += 32) {
            int lb = sAct[l];
            float s = row[lb];
            if (s > 0.0f) {
                unsigned long long p = (la < lb) ? pack_l(s, la, lb) : pack_l(s, lb, la);
                if (p > m) m = p;
            }
        }
        m = warp_max(m);
        if (lane == 0) d_best[la] = m;
    }
}

// ---------------- K7: persistent tail; loads smem C-cache adaptively when n <= CAP ----------------
__global__ void kern_finish(int sel, float* __restrict__ out) {
    extern __shared__ float sC[];              // CAP*CAP floats (dynamic)
    __shared__ int sG[L];
    __shared__ int sCur[L];
    __shared__ int sTmp[L];
    __shared__ int sPos[L];
    __shared__ unsigned long long sBest[L];
    __shared__ int wsum[32];
    __shared__ int sTotal;

    int t = threadIdx.x, lane = t & 31, wid = t >> 5;
    int n = d_nL[sel];
    if (n == 0) return;
    int n0 = d_nAct;
    int ns = (n0 + 31) & ~31;

    for (int x = t; x < n; x += 1024) {
        int la = d_lact[sel][x];
        sCur[x] = la;
        sBest[la] = d_best[la];
        sG[la] = d_act[la];
    }
    __syncthreads();

    bool useC = false;
    int ne = 0;
    while (n > 0) {
        // load C-cache the first time the set fits
        if (!useC && n <= CAP) {
            for (int x = t; x < n; x += 1024) sPos[sCur[x]] = x;
            ne = n;
            for (int idx = t; idx < ne * ne; idx += 1024) {
                int ai = idx / ne, bi2 = idx - ai * ne;
                sC[idx] = d_C[(size_t)sCur[ai] * ns + sCur[bi2]];
            }
            useC = true;
            __syncthreads();
        }

        // ---- take ----
        int f[2]; int vv[2];
        #pragma unroll
        for (int r = 0; r < 2; r++) {
            int idx = 2 * t + r;
            int fl = 0, la = -1;
            if (idx < n) {
                la = sCur[idx];
                unsigned long long b = sBest[la];
                if (b) {
                    unsigned k = ~((unsigned)b);
                    int lo = (int)(k >> LSHIFT), hi = (int)(k & LMASK);
                    int lu = (la == lo) ? hi : lo;
                    if (sBest[lu] == b) {
                        if (la == lo) {
                            float val = __uint_as_float((unsigned)(b >> 32));
                            int gi = sG[lo], gj = sG[hi];
                            out[gi * L + gj] = val;
                            out[gj * L + gi] = val;
                        }
                    } else fl = 1;
                }
            }
            f[r] = fl; vv[r] = la;
        }

        int sum = f[0] + f[1];
        int x = sum;
        #pragma unroll
        for (int o = 1; o < 32; o <<= 1) { int y = __shfl_up_sync(0xFFFFFFFFu, x, o); if (lane >= o) x += y; }
        if (lane == 31) wsum[wid] = x;
        __syncthreads();
        if (wid == 0) {
            int z = wsum[lane];
            #pragma unroll
            for (int o = 1; o < 32; o <<= 1) { int y = __shfl_up_sync(0xFFFFFFFFu, z, o); if (lane >= o) z += y; }
            wsum[lane] = z;
            if (lane == 31) sTotal = z;
        }
        __syncthreads();
        int ex = (wid ? wsum[wid - 1] : 0) + x - sum;
        if (f[0]) sTmp[ex] = vv[0];
        if (f[1]) sTmp[ex + f[0]] = vv[1];
        __syncthreads();
        int nn = sTotal;
        for (int x2 = t; x2 < nn; x2 += 1024) sCur[x2] = sTmp[x2];
        __syncthreads();
        n = nn;
        if (n == 0) break;

        // ---- best ----
        for (int ai = wid; ai < n; ai += 32) {
            int la = sCur[ai];
            int pa = useC ? sPos[la] : 0;
            unsigned long long m = 0ULL;
            for (int li = lane; li < n; li += 32) {
                int lb = sCur[li];
                float s = useC ? sC[pa * ne + sPos[lb]]
                               : d_C[(size_t)la * ns + lb];
                if (s > 0.0f) {
                    unsigned long long p = (la < lb) ? pack_l(s, la, lb) : pack_l(s, lb, la);
                    if (p > m) m = p;
                }
            }
            m = warp_max(m);
            if (lane == 0) sBest[la] = m;
        }
        __syncthreads();
    }
}

// ---------------- launch ----------------
extern "C" void kernel_launch(void* const* d_in, const int* in_sizes, int n_in,
                              void* d_out, int out_size) {
    const float* con  = (const float*)d_in[0];
    const float* feat = (const float*)d_in[1];
    if (n_in >= 2 && in_sizes[0] > in_sizes[1]) {
        const float* tmp = con; con = feat; feat = tmp;
    }
    float* out = (float*)d_out;

    static int smemSet = 0;
    if (!smemSet) {
        cudaFuncSetAttribute(kern_finish, cudaFuncAttributeMaxDynamicSharedMemorySize,
                             CAP * CAP * (int)sizeof(float));
        smemSet = 1;
    }

    const int TRI32 = (L / 32) * (L / 32 + 1) / 2;   // 2080
    const int TRI64 = (L / 64) * (L / 64 + 1) / 2;   // 528
    dim3 tb(32, 32);

    kern_cls<<<8, 256>>>(feat);
    kern_build<<<TRI32, tb>>>(con, out);           // round-1 best + output zeroing
    kern_take1<<<1, 1024>>>(out);                  // -> d_act, clears d_best
    kern_compact<<<TRI64, tb>>>(con);              // 64x64 C gather + round-2 best

    kern_takeL<<<1, 1024>>>(-1, 0, out);           // take round 2
    kern_bestL<<<64, 1024>>>(0);                   // best round 3
    kern_takeL<<<1, 1024>>>(0, 1, out);            // take round 3
    kern_bestL<<<64, 1024>>>(1);                   // best round 4
    kern_takeL<<<1, 1024>>>(1, 0, out);            // take round 4
    kern_bestL<<<64, 1024>>>(0);                   // best round 5

    kern_finish<<<1, 1024, CAP * CAP * (int)sizeof(float)>>>(0, out);  // tail (n ~125)
}

// round 8
// speedup vs baseline: 1.3930x; 1.3930x over previous
#include <cuda_runtime.h>
#include <cuda_bf16.h>

#define L 2048
#define LMASK 2047
#define LSHIFT 11
#define PAIRMASK 0x5A48u
#define CAP 192            // finish smem-cache capacity

// ---------------- device scratch ----------------
__device__ float d_C[(size_t)L * L];          // compacted active x active matrix
__device__ unsigned long long d_best[L];      // per-vertex / per-local-row best priority
__device__ int d_cls[L];
__device__ int d_act[L];                      // global ids of round-1 survivors (ascending)
__device__ int d_nAct;
__device__ int d_lact[2][L];                  // ping-pong local-id lists
__device__ int d_nL[2];

__device__ __forceinline__ unsigned long long pack_g(float s, int a, int b) {
    unsigned k = (unsigned)(a * L + b);
    return ((unsigned long long)__float_as_uint(s) << 32) | (unsigned long long)(~k);
}
__device__ __forceinline__ unsigned long long pack_l(float s, int lo, int hi) {
    unsigned k = ((unsigned)lo << LSHIFT) | (unsigned)hi;
    return ((unsigned long long)__float_as_uint(s) << 32) | (unsigned long long)(~k);
}
__device__ __forceinline__ unsigned long long warp_max(unsigned long long m) {
    #pragma unroll
    for (int o = 16; o; o >>= 1) {
        unsigned long long q = __shfl_xor_sync(0xFFFFFFFFu, m, o);
        if (q > m) m = q;
    }
    return m;
}
// triangular block map: k -> (bi, bj) with bi <= bj
__device__ __forceinline__ void tri_map(int k, int& bi, int& bj) {
    int b = (int)((__fsqrt_rn(8.0f * (float)k + 1.0f) - 1.0f) * 0.5f);
    while (b * (b + 1) / 2 > k) b--;
    while ((b + 1) * (b + 2) / 2 <= k) b++;
    bj = b;
    bi = k - b * (b + 1) / 2;
}

// ---------------- K1: classes + clear best ----------------
__global__ void kern_cls(const float* __restrict__ feat) {
    int i = blockIdx.x * blockDim.x + threadIdx.x;
    if (i >= L) return;
    float f0 = feat[(size_t)i * L];
    float f1 = feat[(size_t)L * L + (size_t)i * L];
    float f2 = feat[2 * (size_t)L * L + (size_t)i * L];
    float f3 = feat[3 * (size_t)L * L + (size_t)i * L];
    int c = 0; float m = f0;
    if (f1 > m) { m = f1; c = 1; }
    if (f2 > m) { m = f2; c = 2; }
    if (f3 > m) { m = f3; c = 3; }
    d_cls[i] = c;
    d_best[i] = 0ULL;
}

// ---------------- K2: round-1 best + zero output (triangular grid, 32x32 tiles) ----------------
__global__ void kern_build(const float* __restrict__ con, float* __restrict__ out) {
    int bi, bj; tri_map(blockIdx.x, bi, bj);      // bi <= bj

    __shared__ float sB[32][33];
    __shared__ int clsR[32], clsC[32];

    int tx = threadIdx.x, ty = threadIdx.y;
    int i = bi * 32 + ty;
    int j = bj * 32 + tx;

    if (ty == 0) { clsR[tx] = d_cls[bi * 32 + tx]; clsC[tx] = d_cls[bj * 32 + tx]; }

    float a = con[(size_t)i * L + j];
    sB[ty][tx] = con[(size_t)(bj * 32 + ty) * L + (bi * 32 + tx)];
    __syncthreads();

    float b = sB[tx][ty];          // con[j][i]
    float v = 0.5f * (a + b);
    int d = j - i;
    bool band = (d >= 4) || (d <= -4);
    bool pm = (PAIRMASK >> ((clsR[ty] << 2) | clsC[tx])) & 1u;
    float s = (band && pm) ? v : 0.0f;

    out[(size_t)i * L + j] = 0.0f;
    out[(size_t)(bj * 32 + ty) * L + (bi * 32 + tx)] = 0.0f;

    // row max (vertex i): pairs (i, j) with j > i
    unsigned long long p = (s > 0.0f && j > i) ? pack_g(s, i, j) : 0ULL;
    unsigned long long m = warp_max(p);
    if (tx == 0 && m) atomicMax(&d_best[i], m);

    // transpose s via sB reuse; recompute priority for column reduction
    __syncthreads();
    sB[ty][tx] = s;
    __syncthreads();
    float s2 = sB[tx][ty];                 // pair (i2 = bi*32+tx, j2 = bj*32+ty)
    int i2 = bi * 32 + tx, j2 = bj * 32 + ty;
    unsigned long long p2 = (s2 > 0.0f && j2 > i2) ? pack_g(s2, i2, j2) : 0ULL;
    unsigned long long cm = warp_max(p2);
    if (tx == 0 && cm) atomicMax(&d_best[j2], cm);
}

// ---------------- K3: round-1 take, build d_act, clear best ----------------
__global__ void kern_take1(float* __restrict__ out) {
    __shared__ int wsum[32];
    __shared__ int sTotal;
    int t = threadIdx.x;
    int lane = t & 31, wid = t >> 5;

    int f[2]; int vv[2];
    #pragma unroll
    for (int r = 0; r < 2; r++) {
        int v = 2 * t + r;
        int fl = 0;
        unsigned long long b = d_best[v];
        if (b) {
            unsigned k = ~((unsigned)b);
            int i = (int)(k >> LSHIFT), j = (int)(k & LMASK);
            int u = (v == i) ? j : i;
            if (d_best[u] == b) {
                if (v == i) {
                    float val = __uint_as_float((unsigned)(b >> 32));
                    out[i * L + j] = val;
                    out[j * L + i] = val;
                }
            } else fl = 1;
        }
        f[r] = fl; vv[r] = v;
    }

    int sum = f[0] + f[1];
    int x = sum;
    #pragma unroll
    for (int o = 1; o < 32; o <<= 1) { int y = __shfl_up_sync(0xFFFFFFFFu, x, o); if (lane >= o) x += y; }
    if (lane == 31) wsum[wid] = x;
    __syncthreads();
    if (wid == 0) {
        int z = wsum[lane];
        #pragma unroll
        for (int o = 1; o < 32; o <<= 1) { int y = __shfl_up_sync(0xFFFFFFFFu, z, o); if (lane >= o) z += y; }
        wsum[lane] = z;
        if (lane == 31) sTotal = z;
    }
    __syncthreads();
    int ex = (wid ? wsum[wid - 1] : 0) + x - sum;
    if (f[0]) d_act[ex] = vv[0];
    if (f[1]) d_act[ex + f[0]] = vv[1];
    if (t == 0) d_nAct = sTotal;

    // clear for compact's local atomicMax (all d_best reads are above)
    d_best[2 * t] = 0ULL;
    d_best[2 * t + 1] = 0ULL;
}

// ---------------- K4: 64x64-tile gather of C + fused round-2 best (triangular grid) ----------------
// 2x2 elements per thread: 8 independent gathered loads -> high MLP.
__global__ void kern_compact(const float* __restrict__ con) {
    int n = d_nAct;
    int bi, bj; tri_map(blockIdx.x, bi, bj);      // 64-tiles, bi <= bj
    if (bi * 64 >= n || bj * 64 >= n) return;
    int ns = (n + 31) & ~31;

    __shared__ float sT[64][65];
    __shared__ int gA[64], gB[64], cA[64], cB[64];

    int tx = threadIdx.x, ty = threadIdx.y;
    int t = ty * 32 + tx;
    if (t < 64) {
        int a = bi * 64 + t;
        int va = (a < n) ? d_act[a] : -1;
        gA[t] = va; cA[t] = (va >= 0) ? d_cls[va] : 0;
    } else if (t < 128) {
        int q = t - 64, b = bj * 64 + q;
        int vb = (b < n) ? d_act[b] : -1;
        gB[q] = vb; cB[q] = (vb >= 0) ? d_cls[vb] : 0;
    }
    __syncthreads();

    int vaR[2] = { gA[ty], gA[ty + 32] };
    int vbR[2] = { gB[tx], gB[tx + 32] };
    int caR[2] = { cA[ty], cA[ty + 32] };
    int cbR[2] = { cB[tx], cB[tx + 32] };

    // direct tile: x[ry][rx] = con[va][vb]  (row-local gathers)
    float x[2][2];
    #pragma unroll
    for (int ry = 0; ry < 2; ry++)
        #pragma unroll
        for (int rx = 0; rx < 2; rx++)
            x[ry][rx] = (vaR[ry] >= 0 && vbR[rx] >= 0)
                      ? con[(size_t)vaR[ry] * L + vbR[rx]] : 0.0f;

    // transposed source tile into smem: sT[q][p] = con[gB[q]][gA[p]]  (row-local gathers)
    {
        int wy[2] = { gB[ty], gB[ty + 32] };
        int ua[2] = { gA[tx], gA[tx + 32] };
        #pragma unroll
        for (int ry = 0; ry < 2; ry++)
            #pragma unroll
            for (int rx = 0; rx < 2; rx++)
                sT[ty + 32 * ry][tx + 32 * rx] =
                    (wy[ry] >= 0 && ua[rx] >= 0)
                  ? con[(size_t)wy[ry] * L + ua[rx]] : 0.0f;
    }
    __syncthreads();

    // masked symmetric value, direct C write, row max
    float s[2][2];
    #pragma unroll
    for (int ry = 0; ry < 2; ry++) {
        int a = bi * 64 + ty + 32 * ry;
        unsigned long long m = 0ULL;
        #pragma unroll
        for (int rx = 0; rx < 2; rx++) {
            int b = bj * 64 + tx + 32 * rx;
            float v = 0.5f * (x[ry][rx] + sT[tx + 32 * rx][ty + 32 * ry]);
            float sv = 0.0f;
            if (vaR[ry] >= 0 && vbR[rx] >= 0) {
                int d = vaR[ry] - vbR[rx];
                bool band = (d >= 4) || (d <= -4);
                bool pm = (PAIRMASK >> ((caR[ry] << 2) | cbR[rx])) & 1u;
                sv = (band && pm) ? v : 0.0f;
            }
            s[ry][rx] = sv;
            if (a < n && b < n) d_C[(size_t)a * ns + b] = sv;   // coalesced over tx
            if (sv > 0.0f && b > a) {
                unsigned long long p = pack_l(sv, a, b);
                if (p > m) m = p;
            }
        }
        m = warp_max(m);
        if (tx == 0 && m) atomicMax(&d_best[a], m);
    }

    // transpose s via smem: mirrored C write + column reduction
    __syncthreads();
    #pragma unroll
    for (int ry = 0; ry < 2; ry++)
        #pragma unroll
        for (int rx = 0; rx < 2; rx++)
            sT[ty + 32 * ry][tx + 32 * rx] = s[ry][rx];
    __syncthreads();

    #pragma unroll
    for (int ry = 0; ry < 2; ry++) {
        int b2 = bj * 64 + ty + 32 * ry;
        unsigned long long m = 0ULL;
        #pragma unroll
        for (int rx = 0; rx < 2; rx++) {
            int a2 = bi * 64 + tx + 32 * rx;
            float s2 = sT[tx + 32 * rx][ty + 32 * ry];
            if (b2 < n && a2 < n) d_C[(size_t)b2 * ns + a2] = s2;   // coalesced over tx
            if (s2 > 0.0f && b2 > a2) {
                unsigned long long p = pack_l(s2, a2, b2);
                if (p > m) m = p;
            }
        }
        m = warp_max(m);
        if (tx == 0 && m) atomicMax(&d_best[b2], m);
    }
}

// ---------------- K5: local-space take (1 block) ----------------
// srcSel < 0: identity list 0..d_nAct
__global__ void kern_takeL(int srcSel, int dstSel, float* __restrict__ out) {
    __shared__ int wsum[32];
    __shared__ int sTotal;
    int t = threadIdx.x;
    int lane = t & 31, wid = t >> 5;
    int n = (srcSel < 0) ? d_nAct : d_nL[srcSel];
    const int* lst = (srcSel < 0) ? 0 : d_lact[srcSel];

    int f[2]; int vv[2];
    #pragma unroll
    for (int r = 0; r < 2; r++) {
        int idx = 2 * t + r;
        int fl = 0, la = -1;
        if (idx < n) {
            la = lst ? lst[idx] : idx;
            unsigned long long b = d_best[la];
            if (b) {
                unsigned k = ~((unsigned)b);
                int lo = (int)(k >> LSHIFT), hi = (int)(k & LMASK);
                int lu = (la == lo) ? hi : lo;
                if (d_best[lu] == b) {
                    if (la == lo) {
                        float val = __uint_as_float((unsigned)(b >> 32));
                        int gi = d_act[lo], gj = d_act[hi];
                        out[gi * L + gj] = val;
                        out[gj * L + gi] = val;
                    }
                } else fl = 1;
            }
        }
        f[r] = fl; vv[r] = la;
    }

    int sum = f[0] + f[1];
    int x = sum;
    #pragma unroll
    for (int o = 1; o < 32; o <<= 1) { int y = __shfl_up_sync(0xFFFFFFFFu, x, o); if (lane >= o) x += y; }
    if (lane == 31) wsum[wid] = x;
    __syncthreads();
    if (wid == 0) {
        int z = wsum[lane];
        #pragma unroll
        for (int o = 1; o < 32; o <<= 1) { int y = __shfl_up_sync(0xFFFFFFFFu, z, o); if (lane >= o) z += y; }
        wsum[lane] = z;
        if (lane == 31) sTotal = z;
    }
    __syncthreads();
    int ex = (wid ? wsum[wid - 1] : 0) + x - sum;
    if (f[0]) d_lact[dstSel][ex] = vv[0];
    if (f[1]) d_lact[dstSel][ex + f[0]] = vv[1];
    if (t == 0) d_nL[dstSel] = sTotal;
}

// ---------------- K6: local-space best over C (multi-CTA, warp per row) ----------------
__global__ void kern_bestL(int sel) {
    __shared__ int sAct[L];
    int n = d_nL[sel];
    if (n == 0) return;
    int ns = (d_nAct + 31) & ~31;
    const int* lst = d_lact[sel];
    for (int t = threadIdx.x; t < n; t += blockDim.x) sAct[t] = lst[t];
    __syncthreads();

    int lane = threadIdx.x & 31;
    int gw = (blockIdx.x * blockDim.x + threadIdx.x) >> 5;
    int tw = (gridDim.x * blockDim.x) >> 5;

    for (int a = gw; a < n; a += tw) {
        int la = sAct[a];
        const float* __restrict__ row = d_C + (size_t)la * ns;
        unsigned long long m = 0ULL;
        for (int l = lane; l < n; l += 32) {
            int lb = sAct[l];
            float s = row[lb];
            if (s > 0.0f) {
                unsigned long long p = (la < lb) ? pack_l(s, la, lb) : pack_l(s, lb, la);
                if (p > m) m = p;
            }
        }
        m = warp_max(m);
        if (lane == 0) d_best[la] = m;
    }
}

// ---------------- K7: persistent tail with smem-cached C submatrix ----------------
__global__ void kern_finish(int sel, float* __restrict__ out) {
    extern __shared__ float sC[];              // CAP*CAP floats (dynamic)
    __shared__ int sG[L];
    __shared__ int sCur[L];
    __shared__ int sTmp[L];
    __shared__ int sPos[L];
    __shared__ unsigned long long sBest[L];
    __shared__ int wsum[32];
    __shared__ int sTotal;

    int t = threadIdx.x, lane = t & 31, wid = t >> 5;
    int n = d_nL[sel];
    if (n == 0) return;
    int n0 = d_nAct;
    int ns = (n0 + 31) & ~31;

    for (int x = t; x < n; x += 1024) {
        int la = d_lact[sel][x];
        sCur[x] = la;
        sPos[la] = x;
        sBest[la] = d_best[la];
        sG[la] = d_act[la];
    }
    __syncthreads();

    bool useC = (n <= CAP);
    int ne = n;
    if (useC) {
        for (int idx = t; idx < ne * ne; idx += 1024) {
            int ai = idx / ne, bi2 = idx - ai * ne;
            sC[idx] = d_C[(size_t)sCur[ai] * ns + sCur[bi2]];
        }
        __syncthreads();
    }

    while (n > 0) {
        // ---- take ----
        int f[2]; int vv[2];
        #pragma unroll
        for (int r = 0; r < 2; r++) {
            int idx = 2 * t + r;
            int fl = 0, la = -1;
            if (idx < n) {
                la = sCur[idx];
                unsigned long long b = sBest[la];
                if (b) {
                    unsigned k = ~((unsigned)b);
                    int lo = (int)(k >> LSHIFT), hi = (int)(k & LMASK);
                    int lu = (la == lo) ? hi : lo;
                    if (sBest[lu] == b) {
                        if (la == lo) {
                            float val = __uint_as_float((unsigned)(b >> 32));
                            int gi = sG[lo], gj = sG[hi];
                            out[gi * L + gj] = val;
                            out[gj * L + gi] = val;
                        }
                    } else fl = 1;
                }
            }
            f[r] = fl; vv[r] = la;
        }

        int sum = f[0] + f[1];
        int x = sum;
        #pragma unroll
        for (int o = 1; o < 32; o <<= 1) { int y = __shfl_up_sync(0xFFFFFFFFu, x, o); if (lane >= o) x += y; }
        if (lane == 31) wsum[wid] = x;
        __syncthreads();
        if (wid == 0) {
            int z = wsum[lane];
            #pragma unroll
            for (int o = 1; o < 32; o <<= 1) { int y = __shfl_up_sync(0xFFFFFFFFu, z, o); if (lane >= o) z += y; }
            wsum[lane] = z;
            if (lane == 31) sTotal = z;
        }
        __syncthreads();
        int ex = (wid ? wsum[wid - 1] : 0) + x - sum;
        if (f[0]) sTmp[ex] = vv[0];
        if (f[1]) sTmp[ex + f[0]] = vv[1];
        __syncthreads();
        int nn = sTotal;
        for (int x2 = t; x2 < nn; x2 += 1024) sCur[x2] = sTmp[x2];
        __syncthreads();
        n = nn;
        if (n == 0) break;

        // ---- best ----
        for (int ai = wid; ai < n; ai += 32) {
            int la = sCur[ai];
            int pa = sPos[la];
            unsigned long long m = 0ULL;
            for (int li = lane; li < n; li += 32) {
                int lb = sCur[li];
                float s = useC ? sC[pa * ne + sPos[lb]]
                               : d_C[(size_t)la * ns + lb];
                if (s > 0.0f) {
                    unsigned long long p = (la < lb) ? pack_l(s, la, lb) : pack_l(s, lb, la);
                    if (p > m) m = p;
                }
            }
            m = warp_max(m);
            if (lane == 0) sBest[la] = m;
        }
        __syncthreads();
    }
}

// ---------------- launch ----------------
extern "C" void kernel_launch(void* const* d_in, const int* in_sizes, int n_in,
                              void* d_out, int out_size) {
    const float* con  = (const float*)d_in[0];
    const float* feat = (const float*)d_in[1];
    if (n_in >= 2 && in_sizes[0] > in_sizes[1]) {
        const float* tmp = con; con = feat; feat = tmp;
    }
    float* out = (float*)d_out;

    static int smemSet = 0;
    if (!smemSet) {
        cudaFuncSetAttribute(kern_finish, cudaFuncAttributeMaxDynamicSharedMemorySize,
                             CAP * CAP * (int)sizeof(float));
        smemSet = 1;
    }

    const int TRI32 = (L / 32) * (L / 32 + 1) / 2;   // 2080
    const int TRI64 = (L / 64) * (L / 64 + 1) / 2;   // 528
    dim3 tb(32, 32);

    kern_cls<<<8, 256>>>(feat);
    kern_build<<<TRI32, tb>>>(con, out);           // round-1 best + output zeroing
    kern_take1<<<1, 1024>>>(out);                  // -> d_act, clears d_best
    kern_compact<<<TRI64, tb>>>(con);              // 64x64 C gather + round-2 best

    kern_takeL<<<1, 1024>>>(-1, 0, out);           // take round 2
    kern_bestL<<<64, 1024>>>(0);                   // best round 3
    kern_takeL<<<1, 1024>>>(0, 1, out);            // take round 3
    kern_bestL<<<64, 1024>>>(1);                   // best round 4
    kern_takeL<<<1, 1024>>>(1, 0, out);            // take round 4
    kern_bestL<<<64, 1024>>>(0);                   // best round 5
    kern_takeL<<<1, 1024>>>(0, 1, out);            // take round 5
    kern_bestL<<<64, 1024>>>(1);                   // best round 6

    kern_finish<<<1, 1024, CAP * CAP * (int)sizeof(float)>>>(1, out);  // tail (n ~64)
}

// round 9
// speedup vs baseline: 1.4387x; 1.0328x over previous
#include <cuda_runtime.h>
#include <cuda_bf16.h>

#define L 2048
#define LMASK 2047
#define LSHIFT 11
#define PAIRMASK 0x5A48u
#define CAP 192            // finish smem-cache capacity

// ---------------- device scratch ----------------
__device__ float d_S[(size_t)L * L];          // masked symmetric matrix
__device__ unsigned long long d_best[L];      // per-vertex best edge priority (global ids)
__device__ int d_cls[L];
__device__ int d_list[2][L];                  // ping-pong active lists (global ids, ascending)
__device__ int d_nL[2];

// priority: value desc, flat index (i*L+j, i<j) asc — exact stable-sort tiebreak
__device__ __forceinline__ unsigned long long pack_g(float s, int i, int j) {
    unsigned k = (unsigned)(i * L + j);
    return ((unsigned long long)__float_as_uint(s) << 32) | (unsigned long long)(~k);
}
__device__ __forceinline__ unsigned long long warp_max(unsigned long long m) {
    #pragma unroll
    for (int o = 16; o; o >>= 1) {
        unsigned long long q = __shfl_xor_sync(0xFFFFFFFFu, m, o);
        if (q > m) m = q;
    }
    return m;
}
// triangular block map: k -> (bi, bj) with bi <= bj
__device__ __forceinline__ void tri_map(int k, int& bi, int& bj) {
    int b = (int)((__fsqrt_rn(8.0f * (float)k + 1.0f) - 1.0f) * 0.5f);
    while (b * (b + 1) / 2 > k) b--;
    while ((b + 1) * (b + 2) / 2 <= k) b++;
    bj = b;
    bi = k - b * (b + 1) / 2;
}

// ---------------- K1: classes + clear best ----------------
__global__ void kern_cls(const float* __restrict__ feat) {
    int i = blockIdx.x * blockDim.x + threadIdx.x;
    if (i >= L) return;
    float f0 = feat[(size_t)i * L];
    float f1 = feat[(size_t)L * L + (size_t)i * L];
    float f2 = feat[2 * (size_t)L * L + (size_t)i * L];
    float f3 = feat[3 * (size_t)L * L + (size_t)i * L];
    int c = 0; float m = f0;
    if (f1 > m) { m = f1; c = 1; }
    if (f2 > m) { m = f2; c = 2; }
    if (f3 > m) { m = f3; c = 3; }
    d_cls[i] = c;
    d_best[i] = 0ULL;
}

// ---------------- K2: masked symmetric S + round-1 best + zero output ----------------
__global__ void kern_build(const float* __restrict__ con, float* __restrict__ out) {
    int bi, bj; tri_map(blockIdx.x, bi, bj);      // bi <= bj

    __shared__ float sB[32][33];
    __shared__ int clsR[32], clsC[32];

    int tx = threadIdx.x, ty = threadIdx.y;
    int i = bi * 32 + ty;
    int j = bj * 32 + tx;

    if (ty == 0) { clsR[tx] = d_cls[bi * 32 + tx]; clsC[tx] = d_cls[bj * 32 + tx]; }

    float a = con[(size_t)i * L + j];
    sB[ty][tx] = con[(size_t)(bj * 32 + ty) * L + (bi * 32 + tx)];
    __syncthreads();

    float b = sB[tx][ty];          // con[j][i]
    float v = 0.5f * (a + b);
    int d = j - i;
    bool band = (d >= 4) || (d <= -4);
    bool pm = (PAIRMASK >> ((clsR[ty] << 2) | clsC[tx])) & 1u;
    float s = (band && pm) ? v : 0.0f;

    out[(size_t)i * L + j] = 0.0f;
    out[(size_t)(bj * 32 + ty) * L + (bi * 32 + tx)] = 0.0f;

    d_S[(size_t)i * L + j] = s;                   // direct tile, coalesced

    // row max (vertex i): pairs (i, j) with j > i
    unsigned long long p = (s > 0.0f && j > i) ? pack_g(s, i, j) : 0ULL;
    unsigned long long m = warp_max(p);
    if (tx == 0 && m) atomicMax(&d_best[i], m);

    // transpose s via sB reuse: mirrored S write + column best
    __syncthreads();
    sB[ty][tx] = s;
    __syncthreads();
    float s2 = sB[tx][ty];                 // value for pair (i2 = bi*32+tx, j2 = bj*32+ty)
    int i2 = bi * 32 + tx, j2 = bj * 32 + ty;
    d_S[(size_t)j2 * L + i2] = s2;                // mirrored tile, coalesced over tx
    unsigned long long p2 = (s2 > 0.0f && j2 > i2) ? pack_g(s2, i2, j2) : 0ULL;
    unsigned long long cm = warp_max(p2);
    if (tx == 0 && cm) atomicMax(&d_best[j2], cm);
}

// ---------------- K3: take (1 block; srcSel<0 = all L vertices) ----------------
__global__ void kern_take(int srcSel, int dstSel, float* __restrict__ out) {
    __shared__ int wsum[32];
    __shared__ int sTotal;
    int t = threadIdx.x;
    int lane = t & 31, wid = t >> 5;
    int n = (srcSel < 0) ? L : d_nL[srcSel];
    const int* lst = (srcSel < 0) ? 0 : d_list[srcSel];

    int f[2]; int vv[2];
    #pragma unroll
    for (int r = 0; r < 2; r++) {
        int idx = 2 * t + r;
        int fl = 0, v = -1;
        if (idx < n) {
            v = lst ? lst[idx] : idx;
            unsigned long long b = d_best[v];
            if (b) {
                unsigned k = ~((unsigned)b);
                int i = (int)(k >> LSHIFT), j = (int)(k & LMASK);
                int u = (v == i) ? j : i;
                if (d_best[u] == b) {
                    if (v == i) {   // write once per pair
                        float val = __uint_as_float((unsigned)(b >> 32));
                        out[i * L + j] = val;
                        out[j * L + i] = val;
                    }
                } else fl = 1;      // survives
            }
        }
        f[r] = fl; vv[r] = v;
    }

    int sum = f[0] + f[1];
    int x = sum;
    #pragma unroll
    for (int o = 1; o < 32; o <<= 1) { int y = __shfl_up_sync(0xFFFFFFFFu, x, o); if (lane >= o) x += y; }
    if (lane == 31) wsum[wid] = x;
    __syncthreads();
    if (wid == 0) {
        int z = wsum[lane];
        #pragma unroll
        for (int o = 1; o < 32; o <<= 1) { int y = __shfl_up_sync(0xFFFFFFFFu, z, o); if (lane >= o) z += y; }
        wsum[lane] = z;
        if (lane == 31) sTotal = z;
    }
    __syncthreads();
    int ex = (wid ? wsum[wid - 1] : 0) + x - sum;
    if (f[0]) d_list[dstSel][ex] = vv[0];
    if (f[1]) d_list[dstSel][ex + f[0]] = vv[1];
    if (t == 0) d_nL[dstSel] = sTotal;
}

// ---------------- K4: best over active set, reading S rows (spread distribution) ----------------
// 256-thread blocks (8 warps); row a -> block (a % gridDim), warp (a/gridDim % 8):
// consecutive rows land on different blocks/SMs -> L1tex work spread chip-wide.
__global__ void kern_bestG(int sel) {
    __shared__ int sAct[L];
    int n = d_nL[sel];
    if (n == 0) return;
    const int* lst = d_list[sel];
    for (int t = threadIdx.x; t < n; t += blockDim.x) sAct[t] = lst[t];
    __syncthreads();

    int lane = threadIdx.x & 31;
    int wid = threadIdx.x >> 5;                       // 0..7
    int start = blockIdx.x * 8 + wid;                 // interleaved over blocks
    int stride = gridDim.x * 8;

    for (int a = start; a < n; a += stride) {
        int v = sAct[a];
        const float* __restrict__ row = d_S + (size_t)v * L;
        unsigned long long m = 0ULL;
        for (int l = lane; l < n; l += 32) {
            int u = sAct[l];
            float s = row[u];
            if (s > 0.0f) {
                unsigned long long p = (v < u) ? pack_g(s, v, u) : pack_g(s, u, v);
                if (p > m) m = p;
            }
        }
        m = warp_max(m);
        if (lane == 0) d_best[v] = m;
    }
}

// ---------------- K5: persistent tail with smem-cached S submatrix ----------------
__global__ void kern_finish(int sel, float* __restrict__ out) {
    extern __shared__ float sC[];              // CAP*CAP floats (dynamic)
    __shared__ int sCur[L];
    __shared__ int sTmp[L];
    __shared__ short sPos[L];
    __shared__ unsigned long long sBest[L];
    __shared__ int wsum[32];
    __shared__ int sTotal;

    int t = threadIdx.x, lane = t & 31, wid = t >> 5;
    int n = d_nL[sel];
    if (n == 0) return;

    for (int x = t; x < n; x += 1024) {
        int v = d_list[sel][x];
        sCur[x] = v;
        sPos[v] = (short)x;
        sBest[v] = d_best[v];
    }
    __syncthreads();

    bool useC = (n <= CAP);
    int ne = n;
    if (useC) {
        for (int idx = t; idx < ne * ne; idx += 1024) {
            int ai = idx / ne, bi2 = idx - ai * ne;
            sC[idx] = d_S[(size_t)sCur[ai] * L + sCur[bi2]];
        }
        __syncthreads();
    }

    while (n > 0) {
        // ---- take ----
        int f[2]; int vv[2];
        #pragma unroll
        for (int r = 0; r < 2; r++) {
            int idx = 2 * t + r;
            int fl = 0, v = -1;
            if (idx < n) {
                v = sCur[idx];
                unsigned long long b = sBest[v];
                if (b) {
                    unsigned k = ~((unsigned)b);
                    int i = (int)(k >> LSHIFT), j = (int)(k & LMASK);
                    int u = (v == i) ? j : i;
                    if (sBest[u] == b) {
                        if (v == i) {
                            float val = __uint_as_float((unsigned)(b >> 32));
                            out[i * L + j] = val;
                            out[j * L + i] = val;
                        }
                    } else fl = 1;
                }
            }
            f[r] = fl; vv[r] = v;
        }

        int sum = f[0] + f[1];
        int x = sum;
        #pragma unroll
        for (int o = 1; o < 32; o <<= 1) { int y = __shfl_up_sync(0xFFFFFFFFu, x, o); if (lane >= o) x += y; }
        if (lane == 31) wsum[wid] = x;
        __syncthreads();
        if (wid == 0) {
            int z = wsum[lane];
            #pragma unroll
            for (int o = 1; o < 32; o <<= 1) { int y = __shfl_up_sync(0xFFFFFFFFu, z, o); if (lane >= o) z += y; }
            wsum[lane] = z;
            if (lane == 31) sTotal = z;
        }
        __syncthreads();
        int ex = (wid ? wsum[wid - 1] : 0) + x - sum;
        if (f[0]) sTmp[ex] = vv[0];
        if (f[1]) sTmp[ex + f[0]] = vv[1];
        __syncthreads();
        int nn = sTotal;
        for (int x2 = t; x2 < nn; x2 += 1024) sCur[x2] = sTmp[x2];
        __syncthreads();
        n = nn;
        if (n == 0) break;

        // ---- best ----
        for (int ai = wid; ai < n; ai += 32) {
            int v = sCur[ai];
            int pa = useC ? sPos[v] : 0;
            unsigned long long m = 0ULL;
            for (int li = lane; li < n; li += 32) {
                int u = sCur[li];
                float s = useC ? sC[pa * ne + sPos[u]]
                               : d_S[(size_t)v * L + u];
                if (s > 0.0f) {
                    unsigned long long p = (v < u) ? pack_g(s, v, u) : pack_g(s, u, v);
                    if (p > m) m = p;
                }
            }
            m = warp_max(m);
            if (lane == 0) sBest[v] = m;
        }
        __syncthreads();
    }
}

// ---------------- launch ----------------
extern "C" void kernel_launch(void* const* d_in, const int* in_sizes, int n_in,
                              void* d_out, int out_size) {
    const float* con  = (const float*)d_in[0];
    const float* feat = (const float*)d_in[1];
    if (n_in >= 2 && in_sizes[0] > in_sizes[1]) {
        const float* tmp = con; con = feat; feat = tmp;
    }
    float* out = (float*)d_out;

    static int smemSet = 0;
    if (!smemSet) {
        cudaFuncSetAttribute(kern_finish, cudaFuncAttributeMaxDynamicSharedMemorySize,
                             CAP * CAP * (int)sizeof(float));
        smemSet = 1;
    }

    const int TRI32 = (L / 32) * (L / 32 + 1) / 2;   // 2080
    dim3 tb(32, 32);

    kern_cls<<<8, 256>>>(feat);
    kern_build<<<TRI32, tb>>>(con, out);           // S + round-1 best + output zeroing

    kern_take<<<1, 1024>>>(-1, 0, out);            // take1 -> list0
    kern_bestG<<<128, 256>>>(0);                   // best2
    kern_take<<<1, 1024>>>(0, 1, out);             // take2
    kern_bestG<<<128, 256>>>(1);                   // best3
    kern_take<<<1, 1024>>>(1, 0, out);             // take3
    kern_bestG<<<128, 256>>>(0);                   // best4
    kern_take<<<1, 1024>>>(0, 1, out);             // take4
    kern_bestG<<<128, 256>>>(1);                   // best5
    kern_take<<<1, 1024>>>(1, 0, out);             // take5
    kern_bestG<<<128, 256>>>(0);                   // best6

    kern_finish<<<1, 1024, CAP * CAP * (int)sizeof(float)>>>(0, out);  // tail (n small)
}